// round 2
// baseline (speedup 1.0000x reference)
#include <cuda_runtime.h>

#define PAD_ID    100000
#define ITEM_ROWS 100001
#define USER_ROWS 100000
#define D   64
#define NB  4096     // batch B
#define L   200
#define NEGW 0.1f

#define NB_G1   296          // item Gram blocks
#define NB_GV   32           // user Gram blocks
#define NB_POS  1024         // pos-loss blocks (4 b each)
#define B_PER_BLK 4
#define CHUNK   64           // rows per smem chunk for Gram

__device__ float g_g1[D * D];
__device__ float g_gv[D * D];
__device__ float g_pos;

__global__ void init_kernel() {
    int t = threadIdx.x;
    for (int i = t; i < D * D; i += blockDim.x) { g_g1[i] = 0.f; g_gv[i] = 0.f; }
    if (t == 0) g_pos = 0.f;
}

__global__ __launch_bounds__(256) void main_kernel(
    const int* __restrict__ uids, const int* __restrict__ pos_iids,
    const float* __restrict__ userW, const float* __restrict__ itemW,
    const float* __restrict__ h)
{
    __shared__ float sm[CHUNK * D];   // 16 KB, reused by both paths
    __shared__ float hh[D];
    __shared__ float warpsum[8];

    int tid = threadIdx.x;
    int bid = blockIdx.x;
    if (tid < D) hh[tid] = h[tid];
    __syncthreads();

    if (bid < NB_G1 + NB_GV) {
        // ---------------- Gram path (item or user) ----------------
        const bool is_item = (bid < NB_G1);
        const int rows_total = is_item ? ITEM_ROWS : NB;
        const int nblk = is_item ? NB_G1 : NB_GV;
        const int gb = is_item ? bid : (bid - NB_G1);
        const int per = (rows_total + nblk - 1) / nblk;
        const int r0 = gb * per;
        const int r1 = min(r0 + per, rows_total);

        const int tx = tid & 15, ty = tid >> 4;
        float c[4][4];
        #pragma unroll
        for (int i = 0; i < 4; i++)
            #pragma unroll
            for (int j = 0; j < 4; j++) c[i][j] = 0.f;

        for (int base = r0; base < r1; base += CHUNK) {
            // load up to CHUNK rows into smem (zero-pad past r1)
            for (int i = tid; i < CHUNK * D; i += 256) {
                int r = base + (i >> 6);
                int d = i & 63;
                float v = 0.f;
                if (r < r1) {
                    if (is_item) v = itemW[(size_t)r * D + d];
                    else         v = userW[(size_t)uids[r] * D + d] * hh[d];
                }
                sm[i] = v;
            }
            __syncthreads();

            #pragma unroll 8
            for (int r = 0; r < CHUNK; r++) {
                float4 a  = *(const float4*)(sm + r * D + ty * 4);
                float4 bb = *(const float4*)(sm + r * D + tx * 4);
                float av[4] = {a.x, a.y, a.z, a.w};
                float bv[4] = {bb.x, bb.y, bb.z, bb.w};
                #pragma unroll
                for (int i = 0; i < 4; i++)
                    #pragma unroll
                    for (int j = 0; j < 4; j++)
                        c[i][j] = fmaf(av[i], bv[j], c[i][j]);
            }
            __syncthreads();
        }

        float* dst = is_item ? g_g1 : g_gv;
        #pragma unroll
        for (int i = 0; i < 4; i++)
            #pragma unroll
            for (int j = 0; j < 4; j++)
                atomicAdd(&dst[(ty * 4 + i) * D + (tx * 4 + j)], c[i][j]);
    } else {
        // ---------------- pos-loss path ----------------
        const int pb = bid - (NB_G1 + NB_GV);
        const int b0 = pb * B_PER_BLK;

        // v[b_local][d] = user_W[uid][d] * h[d]  (256 floats total)
        for (int i = tid; i < B_PER_BLK * D; i += 256) {
            int bl = i >> 6, d = i & 63;
            int uid = uids[b0 + bl];
            sm[i] = userW[(size_t)uid * D + d] * hh[d];
        }
        __syncthreads();

        const int warp = tid >> 5, lane = tid & 31;
        float acc = 0.f;

        for (int bl = 0; bl < B_PER_BLK; bl++) {
            float2 v2 = ((const float2*)(sm + bl * D))[lane];
            const int* pi = pos_iids + (size_t)(b0 + bl) * L;
            // each warp handles pairs (l, l+1); 2-way ILP hides L2 latency
            for (int l = warp * 2; l < L; l += 16) {
                int i1 = pi[l];
                int i2 = pi[l + 1];
                float pa = 0.f, pb2 = 0.f;
                if (i1 != PAD_ID) {
                    float2 r = ((const float2*)(itemW + (size_t)i1 * D))[lane];
                    pa = fmaf(r.x, v2.x, r.y * v2.y);
                }
                if (i2 != PAD_ID) {
                    float2 r = ((const float2*)(itemW + (size_t)i2 * D))[lane];
                    pb2 = fmaf(r.x, v2.x, r.y * v2.y);
                }
                #pragma unroll
                for (int o = 16; o > 0; o >>= 1) {
                    pa  += __shfl_xor_sync(0xffffffffu, pa, o);
                    pb2 += __shfl_xor_sync(0xffffffffu, pb2, o);
                }
                acc += (1.0f - NEGW) * (pa * pa + pb2 * pb2) - 2.0f * (pa + pb2);
            }
        }

        if (lane == 0) warpsum[warp] = acc;
        __syncthreads();
        if (tid == 0) {
            float s = 0.f;
            #pragma unroll
            for (int w = 0; w < 8; w++) s += warpsum[w];
            atomicAdd(&g_pos, s);
        }
    }
}

__global__ void combine_kernel(float* __restrict__ out) {
    __shared__ float red[256];
    int tid = threadIdx.x;
    float s = 0.f;
    for (int e = tid; e < D * D; e += 256) s += g_g1[e] * g_gv[e];
    red[tid] = s;
    __syncthreads();
    for (int off = 128; off > 0; off >>= 1) {
        if (tid < off) red[tid] += red[tid + off];
        __syncthreads();
    }
    if (tid == 0) out[0] = NEGW * red[0] + g_pos;
}

extern "C" void kernel_launch(void* const* d_in, const int* in_sizes, int n_in,
                              void* d_out, int out_size) {
    const int*   uids     = (const int*)d_in[0];
    const int*   pos_iids = (const int*)d_in[1];
    const float* userW    = (const float*)d_in[2];
    const float* itemW    = (const float*)d_in[3];
    const float* h        = (const float*)d_in[4];
    float* out = (float*)d_out;

    init_kernel<<<1, 256>>>();
    main_kernel<<<NB_G1 + NB_GV + NB_POS, 256>>>(uids, pos_iids, userW, itemW, h);
    combine_kernel<<<1, 256>>>(out);
}

// round 5
// speedup vs baseline: 1.0801x; 1.0801x over previous
#include <cuda_runtime.h>

#define PAD_ID    100000
#define ITEM_ROWS 100001
#define D   64
#define NB  4096
#define L   200
#define NEGW 0.1f

#define NB_G1   296            // item Gram blocks
#define NB_GV   32             // user Gram blocks
#define NB_GRAM (NB_G1 + NB_GV)   // 328
#define NB_POS  1024           // pos-loss blocks
#define B_PER_BLK 4
#define CHUNK   64
#define GRID_TOTAL (NB_GRAM + NB_POS)   // 1352

// zero-initialized at module load; last block resets them each run
__device__ float g_g1[D * D];
__device__ float g_gv[D * D];
__device__ float g_pos;
__device__ unsigned int g_done;

__global__ __launch_bounds__(256) void enmf_kernel(
    const int* __restrict__ uids, const int* __restrict__ pos_iids,
    const float* __restrict__ userW, const float* __restrict__ itemW,
    const float* __restrict__ h, float* __restrict__ out)
{
    __shared__ float sm[CHUNK * D];   // 16 KB, reused by all paths
    __shared__ float hh[D];
    __shared__ float warpsum[8];
    __shared__ unsigned int s_rank;

    const int tid = threadIdx.x;
    const int bid = blockIdx.x;
    if (tid < D) hh[tid] = h[tid];
    __syncthreads();

    // ---- interleave block types so FMA-bound and L2-bound blocks co-reside ----
    int gram_id = -1, pos_id = -1;
    if (bid < NB_GRAM * 4) {
        if ((bid & 3) == 3) gram_id = bid >> 2;
        else                pos_id  = (bid >> 2) * 3 + (bid & 3);
    } else {
        pos_id = NB_GRAM * 3 + (bid - NB_GRAM * 4);
    }

    if (gram_id >= 0) {
        // ================= Gram path (upper triangle only) =================
        const bool is_item   = (gram_id < NB_G1);
        const int rows_total = is_item ? ITEM_ROWS : NB;
        const int nblk       = is_item ? NB_G1 : NB_GV;
        const int gb         = is_item ? gram_id : gram_id - NB_G1;
        const int per        = (rows_total + nblk - 1) / nblk;
        const int r0         = gb * per;
        const int r1         = min(r0 + per, rows_total);

        // map tid -> upper-triangle 4x4 tile (ti <= tj) of the 16x16 tile grid
        const bool active = (tid < 136);
        int ti = 0, tj = 0;
        if (active) {
            int tt = tid;
            while (tt >= 16 - ti) { tt -= 16 - ti; ti++; }
            tj = ti + tt;
        }

        float c[4][4];
        #pragma unroll
        for (int i = 0; i < 4; i++)
            #pragma unroll
            for (int j = 0; j < 4; j++) c[i][j] = 0.f;

        float4* smv = (float4*)sm;
        const float4* hv4 = (const float4*)hh;

        for (int base = r0; base < r1; base += CHUNK) {
            // fill CHUNK x D chunk with float4 loads (zero-pad past r1)
            for (int i = tid; i < CHUNK * 16; i += 256) {
                int r = base + (i >> 4);
                float4 v = make_float4(0.f, 0.f, 0.f, 0.f);
                if (r < r1) {
                    if (is_item) {
                        v = ((const float4*)itemW)[(size_t)r * 16 + (i & 15)];
                    } else {
                        float4 u = ((const float4*)userW)[(size_t)uids[r] * 16 + (i & 15)];
                        float4 hx = hv4[i & 15];
                        v = make_float4(u.x * hx.x, u.y * hx.y, u.z * hx.z, u.w * hx.w);
                    }
                }
                smv[i] = v;
            }
            __syncthreads();

            if (active) {
                #pragma unroll 8
                for (int r = 0; r < CHUNK; r++) {
                    float4 a = smv[r * 16 + ti];
                    float4 b = smv[r * 16 + tj];
                    float av[4] = {a.x, a.y, a.z, a.w};
                    float bv[4] = {b.x, b.y, b.z, b.w};
                    #pragma unroll
                    for (int i = 0; i < 4; i++)
                        #pragma unroll
                        for (int j = 0; j < 4; j++)
                            c[i][j] = fmaf(av[i], bv[j], c[i][j]);
                }
            }
            __syncthreads();
        }

        if (active) {
            float* dst = is_item ? g_g1 : g_gv;
            #pragma unroll
            for (int i = 0; i < 4; i++)
                #pragma unroll
                for (int j = 0; j < 4; j++) {
                    // keep the stored matrix strictly upper-triangular:
                    // for diagonal tiles skip within-tile lower triangle
                    if (!(ti == tj && j < i))
                        atomicAdd(&dst[(ti * 4 + i) * D + (tj * 4 + j)], c[i][j]);
                }
        }
    } else {
        // ================= pos-loss path (4-way ILP) =================
        const int b0 = pos_id * B_PER_BLK;

        for (int i = tid; i < B_PER_BLK * D; i += 256) {
            int bl = i >> 6, d = i & 63;
            sm[i] = userW[(size_t)uids[b0 + bl] * D + d] * hh[d];
        }
        __syncthreads();

        const int warp = tid >> 5, lane = tid & 31;
        float acc = 0.f;   // after per-pair butterfly, every lane holds warp total

        for (int bl = 0; bl < B_PER_BLK; bl++) {
            float2 v2 = ((const float2*)(sm + bl * D))[lane];
            const int* pi = pos_iids + (size_t)(b0 + bl) * L;

            for (int l = warp * 4; l < L; l += 32) {
                int4 id = ((const int4*)pi)[l >> 2];
                float p0 = 0.f, p1 = 0.f, p2 = 0.f, p3 = 0.f;
                if (id.x != PAD_ID) {
                    float2 r = ((const float2*)(itemW + (size_t)id.x * D))[lane];
                    p0 = fmaf(r.x, v2.x, r.y * v2.y);
                }
                if (id.y != PAD_ID) {
                    float2 r = ((const float2*)(itemW + (size_t)id.y * D))[lane];
                    p1 = fmaf(r.x, v2.x, r.y * v2.y);
                }
                if (id.z != PAD_ID) {
                    float2 r = ((const float2*)(itemW + (size_t)id.z * D))[lane];
                    p2 = fmaf(r.x, v2.x, r.y * v2.y);
                }
                if (id.w != PAD_ID) {
                    float2 r = ((const float2*)(itemW + (size_t)id.w * D))[lane];
                    p3 = fmaf(r.x, v2.x, r.y * v2.y);
                }
                #pragma unroll
                for (int o = 16; o > 0; o >>= 1) {
                    p0 += __shfl_xor_sync(0xffffffffu, p0, o);
                    p1 += __shfl_xor_sync(0xffffffffu, p1, o);
                    p2 += __shfl_xor_sync(0xffffffffu, p2, o);
                    p3 += __shfl_xor_sync(0xffffffffu, p3, o);
                }
                acc += (1.0f - NEGW) * (p0 * p0 + p1 * p1 + p2 * p2 + p3 * p3)
                     - 2.0f * (p0 + p1 + p2 + p3);
            }
        }

        // acc is identical on all lanes — take lane 0's copy ONCE (R3 bug: 32x)
        if (lane == 0) warpsum[warp] = acc;
        __syncthreads();
        if (tid == 0) {
            float s = 0.f;
            #pragma unroll
            for (int w = 0; w < 8; w++) s += warpsum[w];
            atomicAdd(&g_pos, s);
        }
    }

    // ================= last block combines + resets =================
    __threadfence();
    __syncthreads();
    if (tid == 0) s_rank = atomicAdd(&g_done, 1u);
    __syncthreads();

    if (s_rank == GRID_TOTAL - 1) {
        volatile float* v1 = g_g1;
        volatile float* v2 = g_gv;
        float s = 0.f;
        for (int e = tid; e < D * D; e += 256) {
            int i = e >> 6, j = e & 63;
            float w = (i == j) ? 1.f : 2.f;     // mirror the strict upper triangle
            s += w * v1[e] * v2[e];
        }
        sm[tid] = s;
        __syncthreads();
        for (int off = 128; off > 0; off >>= 1) {
            if (tid < off) sm[tid] += sm[tid + off];
            __syncthreads();
        }
        if (tid == 0) {
            out[0] = NEGW * sm[0] + *(volatile float*)&g_pos;
            g_pos = 0.f;
            g_done = 0u;
        }
        for (int e = tid; e < D * D; e += 256) { g_g1[e] = 0.f; g_gv[e] = 0.f; }
    }
}

extern "C" void kernel_launch(void* const* d_in, const int* in_sizes, int n_in,
                              void* d_out, int out_size) {
    const int*   uids     = (const int*)d_in[0];
    const int*   pos_iids = (const int*)d_in[1];
    const float* userW    = (const float*)d_in[2];
    const float* itemW    = (const float*)d_in[3];
    const float* h        = (const float*)d_in[4];
    float* out = (float*)d_out;

    enmf_kernel<<<GRID_TOTAL, 256>>>(uids, pos_iids, userW, itemW, h, out);
}